// round 7
// baseline (speedup 1.0000x reference)
#include <cuda_runtime.h>
#include <float.h>

typedef unsigned long long ull;
#define FULLMASK 0xFFFFFFFFu

// ---------------------------------------------------------------------------
// MID_LOSS: B=8192, E=512, M=8, C=14, BETA=0.3
// x [B, E*M] f32 (layout: e-major, m contiguous), y [B,C] i32, w [E,C] f32
// ---------------------------------------------------------------------------

static __device__ float g_gram[196];       // w^T w  [14,14]
static __device__ float g_partials[888];   // per-block loss sums

__device__ __forceinline__ ull ffma2(ull a, ull b, ull c) {
    ull d;
    asm("fma.rn.f32x2 %0, %1, %2, %3;" : "=l"(d) : "l"(a), "l"(b), "l"(c));
    return d;
}
__device__ __forceinline__ float softplus_f(float v) {
    return fmaxf(v, 0.0f) + log1pf(expf(-fabsf(v)));
}

// ---------------------------------------------------------------------------
// Gram: 13 blocks x 512 thr, one warp per (c,c2) pair
// ---------------------------------------------------------------------------
__global__ void gram_kernel(const float* __restrict__ w) {
    const int g = blockIdx.x * 16 + (threadIdx.x >> 5);
    const int lane = threadIdx.x & 31;
    if (g >= 196) return;
    const int c = g / 14, c2 = g - (g / 14) * 14;
    float s = 0.0f;
    #pragma unroll
    for (int k = 0; k < 16; ++k) {
        int e = lane + 32 * k;
        s += w[e * 14 + c] * w[e * 14 + c2];
    }
    #pragma unroll
    for (int o = 16; o; o >>= 1) s += __shfl_xor_sync(FULLMASK, s, o);
    if (lane == 0) g_gram[g] = s;
}

// ---------------------------------------------------------------------------
// Main: 888 blocks x 256 threads; one sample at a time across all 8 warps.
// warp bits: eh = wid>>2 (e-half), mg = ((wid>>1)&1)*4, cg = (wid&1)*7
// w held in registers (4 i-steps x 7 c as f32x2). x transposed through smem.
// ---------------------------------------------------------------------------
__global__ __launch_bounds__(256) void main_kernel(const float* __restrict__ x,
                                                   const int*   __restrict__ y,
                                                   const float* __restrict__ w) {
    // un_s: [m][257] f32x2 pairs (16456 B) overlaid on w staging area (28672 B)
    __shared__ __align__(16) char sraw[28672];
    __shared__ float dot_part[2][2][112];   // [parity][e-half][m*14+c]
    __shared__ float l1p[2][8];             // [parity][warp]
    __shared__ float dc[2][16];             // [parity][c] column maxes

    const int tid  = threadIdx.x;
    const int lane = tid & 31;
    const int wid  = tid >> 5;
    const int eh = wid >> 2;
    const int mg = ((wid >> 1) & 1) * 4;
    const int cg = (wid & 1) * 7;

    // ---- stage w transposed [c][e] in smem, then hoist to registers ----
    {
        float* ws = (float*)sraw;
        for (int i = tid; i < 7168; i += 256) {
            int e = i / 14, c = i - e * 14;
            ws[c * 512 + e] = w[i];
        }
    }
    __syncthreads();
    ull wr[4][7];
    {
        const float* ws = (const float*)sraw;
        #pragma unroll
        for (int i = 0; i < 4; ++i) {
            const int e0 = 2 * lane + 64 * i + 256 * eh;
            #pragma unroll
            for (int ci = 0; ci < 7; ++ci)
                wr[i][ci] = *(const ull*)(ws + (cg + ci) * 512 + e0);
        }
    }
    __syncthreads();

    // ---- prologue: load x for first sample (thread owns e-pair = tid) ----
    float4 xr0, xr1, xr2, xr3;
    {
        const float4* p = (const float4*)(x + (size_t)blockIdx.x * 4096) + tid * 4;
        xr0 = p[0]; xr1 = p[1]; xr2 = p[2]; xr3 = p[3];
    }

    float block_sum = 0.0f;
    int par = 0;

    for (int s = blockIdx.x; s < 8192; s += 888, par ^= 1) {
        // ---- transpose STS: un[m][ep] = (x[e][m], x[e+1][m]) ----
        {
            float2* u2 = (float2*)sraw;
            u2[0 * 257 + tid] = make_float2(xr0.x, xr2.x);
            u2[1 * 257 + tid] = make_float2(xr0.y, xr2.y);
            u2[2 * 257 + tid] = make_float2(xr0.z, xr2.z);
            u2[3 * 257 + tid] = make_float2(xr0.w, xr2.w);
            u2[4 * 257 + tid] = make_float2(xr1.x, xr3.x);
            u2[5 * 257 + tid] = make_float2(xr1.y, xr3.y);
            u2[6 * 257 + tid] = make_float2(xr1.z, xr3.z);
            u2[7 * 257 + tid] = make_float2(xr1.w, xr3.w);
        }
        // ---- l1 term from registers (var over m, per e) ----
        {
            float s1 = xr0.x + xr0.y + xr0.z + xr0.w + xr1.x + xr1.y + xr1.z + xr1.w;
            float q1 = xr0.x*xr0.x + xr0.y*xr0.y + xr0.z*xr0.z + xr0.w*xr0.w
                     + xr1.x*xr1.x + xr1.y*xr1.y + xr1.z*xr1.z + xr1.w*xr1.w;
            float s2 = xr2.x + xr2.y + xr2.z + xr2.w + xr3.x + xr3.y + xr3.z + xr3.w;
            float q2 = xr2.x*xr2.x + xr2.y*xr2.y + xr2.z*xr2.z + xr2.w*xr2.w
                     + xr3.x*xr3.x + xr3.y*xr3.y + xr3.z*xr3.z + xr3.w*xr3.w;
            float va = (q1 - s1 * s1 * 0.125f) * (1.0f / 7.0f);
            float vb = (q2 - s2 * s2 * 0.125f) * (1.0f / 7.0f);
            float l1t = fabsf(va) + fabsf(vb);
            #pragma unroll
            for (int o = 16; o; o >>= 1) l1t += __shfl_xor_sync(FULLMASK, l1t, o);
            if (lane == 0) l1p[par][wid] = l1t;
        }
        __syncthreads();

        // ---- prefetch next sample's x (hidden under GEMM) ----
        {
            int sn = s + 888;
            const float4* p = (const float4*)(x + (size_t)(sn < 8192 ? sn : s) * 4096) + tid * 4;
            xr0 = p[0]; xr1 = p[1]; xr2 = p[2]; xr3 = p[3];
        }

        // ---- GEMM tile: 4m x 7c over this warp's e-half ----
        ull acc[4][7];
        #pragma unroll
        for (int mi = 0; mi < 4; ++mi)
            #pragma unroll
            for (int ci = 0; ci < 7; ++ci) acc[mi][ci] = 0ull;

        {
            const ull* ab = (const ull*)sraw + mg * 257 + 128 * eh + lane;
            #pragma unroll
            for (int i = 0; i < 4; ++i) {
                ull a2[4];
                #pragma unroll
                for (int mi = 0; mi < 4; ++mi) a2[mi] = ab[mi * 257 + 32 * i];
                #pragma unroll
                for (int mi = 0; mi < 4; ++mi)
                    #pragma unroll
                    for (int ci = 0; ci < 7; ++ci)
                        acc[mi][ci] = ffma2(a2[mi], wr[i][ci], acc[mi][ci]);
            }
        }

        // ---- merge-halving lane reduction: 31 shfl total ----
        {
            float v[32];
            #pragma unroll
            for (int mi = 0; mi < 4; ++mi)
                #pragma unroll
                for (int ci = 0; ci < 7; ++ci) {
                    float lo, hi;
                    asm("mov.b64 {%0,%1}, %2;" : "=f"(lo), "=f"(hi) : "l"(acc[mi][ci]));
                    v[mi * 7 + ci] = lo + hi;
                }
            v[28] = 0.0f; v[29] = 0.0f; v[30] = 0.0f; v[31] = 0.0f;

            float u16[16];
            #pragma unroll
            for (int j = 0; j < 16; ++j) {
                bool h = (lane & 16) != 0;
                float send = h ? v[2*j] : v[2*j+1];
                float keep = h ? v[2*j+1] : v[2*j];
                u16[j] = keep + __shfl_xor_sync(FULLMASK, send, 16);
            }
            float u8[8];
            #pragma unroll
            for (int j = 0; j < 8; ++j) {
                bool h = (lane & 8) != 0;
                float send = h ? u16[2*j] : u16[2*j+1];
                float keep = h ? u16[2*j+1] : u16[2*j];
                u8[j] = keep + __shfl_xor_sync(FULLMASK, send, 8);
            }
            float u4[4];
            #pragma unroll
            for (int j = 0; j < 4; ++j) {
                bool h = (lane & 4) != 0;
                float send = h ? u8[2*j] : u8[2*j+1];
                float keep = h ? u8[2*j+1] : u8[2*j];
                u4[j] = keep + __shfl_xor_sync(FULLMASK, send, 4);
            }
            float u2a[2];
            #pragma unroll
            for (int j = 0; j < 2; ++j) {
                bool h = (lane & 2) != 0;
                float send = h ? u4[2*j] : u4[2*j+1];
                float keep = h ? u4[2*j+1] : u4[2*j];
                u2a[j] = keep + __shfl_xor_sync(FULLMASK, send, 2);
            }
            float r;
            {
                bool h = (lane & 1) != 0;
                float send = h ? u2a[0] : u2a[1];
                float keep = h ? u2a[1] : u2a[0];
                r = keep + __shfl_xor_sync(FULLMASK, send, 1);
            }
            // lane l holds full sum of v[brev5(l)]
            int idx = __brev((unsigned)lane) >> 27;
            if (idx < 28) {
                int mi = idx / 7, ci = idx - mi * 7;
                dot_part[par][eh][(mg + mi) * 14 + (cg + ci)] = r;
            }
        }
        __syncthreads();

        // ---- epilogue: warp 0 ----
        if (wid == 0) {
            const bool inc = lane < 14;
            float dmax = -FLT_MAX;
            if (inc) {
                #pragma unroll
                for (int m = 0; m < 8; ++m) {
                    float d = dot_part[par][0][m * 14 + lane] + dot_part[par][1][m * 14 + lane];
                    dmax = fmaxf(dmax, d);
                }
                dc[par][lane] = dmax;
            }
            int yv = inc ? y[s * 14 + lane] : 0;
            unsigned pm = __ballot_sync(FULLMASK, inc && (yv == 1));
            unsigned nm = (~pm) & 0x3FFFu;
            const int npos = __popc(pm);
            const int nneg = __popc(nm);
            __syncwarp();

            float sloc = 0.0f, diag = 0.0f, row = 0.0f;
            const bool isp = inc && ((pm >> lane) & 1);
            if (isp) {
                const float dp = dmax;
                if (nneg > 0) {
                    #pragma unroll
                    for (int n = 0; n < 14; ++n)
                        if ((nm >> n) & 1) sloc += softplus_f(dc[par][n] - dp);
                } else {
                    sloc = softplus_f(-dp);
                }
                diag = g_gram[lane * 14 + lane];
                #pragma unroll
                for (int c2 = 0; c2 < 14; ++c2)
                    if ((pm >> c2) & 1) row += g_gram[lane * 14 + c2];
            }
            #pragma unroll
            for (int o = 16; o; o >>= 1) {
                sloc += __shfl_xor_sync(FULLMASK, sloc, o);
                diag += __shfl_xor_sync(FULLMASK, diag, o);
                row  += __shfl_xor_sync(FULLMASK, row,  o);
            }
            if (lane == 0) {
                const float npf = (float)npos;
                float tv = 0.0f;
                if (npos > 1) tv = (diag - row / npf) / (npf - 1.0f);
                const float base = sloc / npf;
                const float l1t = l1p[par][0] + l1p[par][1] + l1p[par][2] + l1p[par][3]
                                + l1p[par][4] + l1p[par][5] + l1p[par][6] + l1p[par][7];
                block_sum += 2.0f * (0.7f * (1.0f + tv) * base + 0.3f * l1t);
            }
        }
    }

    if (tid == 0) g_partials[blockIdx.x] = block_sum;
}

// ---------------------------------------------------------------------------
// Final deterministic reduction: 888 partials -> mean
// ---------------------------------------------------------------------------
__global__ void reduce_kernel(float* __restrict__ out) {
    const int tid = threadIdx.x;   // 1024 threads
    float v = (tid < 888) ? g_partials[tid] : 0.0f;
    #pragma unroll
    for (int o = 16; o; o >>= 1) v += __shfl_xor_sync(FULLMASK, v, o);
    __shared__ float red[32];
    if ((tid & 31) == 0) red[tid >> 5] = v;
    __syncthreads();
    if (tid < 32) {
        float s = red[tid];
        #pragma unroll
        for (int o = 16; o; o >>= 1) s += __shfl_xor_sync(FULLMASK, s, o);
        if (tid == 0) out[0] = s * (1.0f / 8192.0f);
    }
}

extern "C" void kernel_launch(void* const* d_in, const int* in_sizes, int n_in,
                              void* d_out, int out_size) {
    const float* x = (const float*)d_in[0];
    const int*   y = (const int*)d_in[1];
    const float* w = (const float*)d_in[2];

    gram_kernel<<<13, 512>>>(w);
    main_kernel<<<888, 256>>>(x, y, w);
    reduce_kernel<<<1, 1024>>>((float*)d_out);
}